// round 13
// baseline (speedup 1.0000x reference)
#include <cuda_runtime.h>
#include <cuda_pipeline.h>
#include <cstdint>

#define NN 256   // nodes
#define FF 256   // feature dim
#define BB 32    // batch
#define EE 8192  // edges
#define CSR_CAP 12288   // padded entries: EE + NN*7 = 9984 max
#define SPAN_CAP 6144   // per-half staged entries

// Global padded CSR (built once by prep): rows padded to multiples of 8,
// pad entries {src=0, w=0.0f} are mathematical no-ops.
__device__ int g_row_ptr[NN + 1];
__device__ __align__(16) int2 g_csr[CSR_CAP];  // .x=src, .y=bits of cos/32

// ---------------------------------------------------------------------------
// Prep (1 block, 1024 threads, parallel scan): count, pad, scan, fill.
// ---------------------------------------------------------------------------
__global__ void __launch_bounds__(1024)
ep_prep_kernel(const float* __restrict__ phase,
               const int* __restrict__ src32,
               const int* __restrict__ dst32) {
    __shared__ int s_cnt[NN];
    __shared__ int s_rp[NN + 1];
    __shared__ int s_off[NN];
    __shared__ int s_is64;
    const int t    = threadIdx.x;
    const int warp = t >> 5;
    const int lane = t & 31;

    if (t == 0) {
        int ok = 1;
        for (int i = 0; i < 64; i++) {
            int lo = dst32[2 * i];
            int hi = dst32[2 * i + 1];
            if (hi != 0 || lo < 0 || lo >= NN) { ok = 0; break; }
        }
        s_is64 = ok;
    }
    if (t < NN) s_cnt[t] = 0;
    __syncthreads();
    const int stride = s_is64 ? 2 : 1;

    for (int e = t; e < EE; e += 1024)
        atomicAdd(&s_cnt[dst32[e * stride]], 1);
    __syncthreads();

    // warp 0: exclusive scan of 256 padded counts (8 per lane).
    if (warp == 0) {
        const int i0 = lane * 8;
        int c[8], tot = 0;
#pragma unroll
        for (int u = 0; u < 8; u++) { c[u] = (s_cnt[i0 + u] + 7) & ~7; tot += c[u]; }
        int pre = tot;
        for (int off = 1; off < 32; off <<= 1) {
            const int v = __shfl_up_sync(0xFFFFFFFFu, pre, off);
            if (lane >= off) pre += v;
        }
        int acc = pre - tot;
#pragma unroll
        for (int u = 0; u < 8; u++) { s_rp[i0 + u] = acc; acc += c[u]; }
        if (lane == 31) s_rp[NN] = acc;
    }
    __syncthreads();

    // publish row_ptr, init fill cursors, zero pad slots.
    if (t < NN + 1) g_row_ptr[t] = s_rp[t];
    if (t < NN) {
        s_off[t] = s_rp[t];
        const int fe = s_rp[t] + s_cnt[t];
        const int re = s_rp[t + 1];
        for (int i = fe; i < re; i++) g_csr[i] = make_int2(0, 0);
    }
    __syncthreads();

    // fill with premultiplied weights.
    for (int e = t; e < EE; e += 1024) {
        const int d = dst32[e * stride];
        const int s = src32[e * stride];
        const int pos = atomicAdd(&s_off[d], 1);
        const float c = cosf(phase[s * NN + d]) * (1.0f / 32.0f);
        g_csr[pos] = make_int2(s, __float_as_int(c));
    }
}

// ---------------------------------------------------------------------------
// Compute: block = (f-tile of 4) x (half of dst range). Grid 128, 1024 thr.
// SMEM: x slice (128KB) + CSR span (48KB) via cp.async; per-warp staging.
// One warp per dst node (lane=batch), 4 nodes per warp, SOFTWARE-PIPELINED:
// node k+1's CSR reads + 2 divergent W LDG.128s issue before node k's
// consume, hiding the gather latency behind consume issue.
// ---------------------------------------------------------------------------
__global__ void __launch_bounds__(1024, 1)
ep_compute_kernel(const float* __restrict__ x,   // [B, N, F]
                  const float* __restrict__ W,   // [N, N, F]
                  float* __restrict__ out) {     // [B, N, F]
    extern __shared__ char s_raw[];
    float4* s_x  = reinterpret_cast<float4*>(s_raw);               // 128KB
    int2*  s_csr = reinterpret_cast<int2*>(s_raw + NN * BB * 16);  // 48KB
    __shared__ float4 s_wc[32][64];
    __shared__ int    s_ss[32][64];
    __shared__ int    s_rp[128 + 1];

    const int bx     = blockIdx.x;
    const int f0     = (bx >> 1) * 4;
    const int n_base = (bx & 1) * 128;
    const int t      = threadIdx.x;
    const int warp   = t >> 5;
    const int lane   = t & 31;

    // async stage: x tile + CSR span + row pointers.
    for (int i = t; i < NN * BB; i += 1024) {
        const int s = i >> 5;
        const int b = i & 31;
        __pipeline_memcpy_async(&s_x[i],
                                x + (size_t)(b * NN + s) * FF + f0,
                                sizeof(float4));
    }
    if (t < 128 + 1) s_rp[t] = g_row_ptr[n_base + t];
    __syncthreads();                       // s_rp visible
    const int cbeg = s_rp[0];
    const int span = s_rp[128] - cbeg;     // multiple of 8
    for (int i = t; i * 2 < span; i += 1024)
        __pipeline_memcpy_async(reinterpret_cast<int4*>(s_csr) + i,
                                reinterpret_cast<const int4*>(g_csr + cbeg) + i,
                                sizeof(int4));
    __pipeline_commit();
    __pipeline_wait_prior(0);
    __syncthreads();

    float4* wcbuf = s_wc[warp];
    int*    ssbuf = s_ss[warp];

    // ---- pipelined node loop: 4 nodes per warp ----
    int p  = s_rp[warp] - cbeg;
    int pe = s_rp[warp + 1] - cbeg;
    const float* Wn = W + (size_t)(n_base + warp) * FF + f0;

    int2 e0 = make_int2(0, 0), e1 = make_int2(0, 0);
    float4 w0 = make_float4(0.f, 0.f, 0.f, 0.f);
    float4 w1 = make_float4(0.f, 0.f, 0.f, 0.f);
    {   // A(0): first chunk of node 0
        const bool v0 = (p + lane < pe);
        const bool v1 = (p + 32 + lane < pe);
        if (v0) e0 = s_csr[p + lane];
        if (v1) e1 = s_csr[p + 32 + lane];
        if (v0) w0 = __ldg(reinterpret_cast<const float4*>(Wn + (size_t)e0.x * (NN * FF)));
        if (v1) w1 = __ldg(reinterpret_cast<const float4*>(Wn + (size_t)e1.x * (NN * FF)));
    }

    for (int k = 0; k < 4; k++) {
        // B(k): premult + store to staging
        {
            const float c0 = __int_as_float(e0.y);
            const float c1 = __int_as_float(e1.y);
            wcbuf[lane]      = make_float4(w0.x * c0, w0.y * c0, w0.z * c0, w0.w * c0);
            ssbuf[lane]      = e0.x;
            wcbuf[32 + lane] = make_float4(w1.x * c1, w1.y * c1, w1.z * c1, w1.w * c1);
            ssbuf[32 + lane] = e1.x;
        }
        __syncwarp();

        const int   curp  = p;
        const int   curpe = pe;
        const float* curWn = Wn;
        const int   curn  = n_base + warp + (k << 5);

        // A(k+1): issue next node's loads while consuming this one
        if (k < 3) {
            const int nl = warp + ((k + 1) << 5);
            p  = s_rp[nl] - cbeg;
            pe = s_rp[nl + 1] - cbeg;
            Wn = W + (size_t)(n_base + nl) * FF + f0;
            const bool v0 = (p + lane < pe);
            const bool v1 = (p + 32 + lane < pe);
            e0 = v0 ? s_csr[p + lane]      : make_int2(0, 0);
            e1 = v1 ? s_csr[p + 32 + lane] : make_int2(0, 0);
            w0 = make_float4(0.f, 0.f, 0.f, 0.f);
            w1 = make_float4(0.f, 0.f, 0.f, 0.f);
            if (v0) w0 = __ldg(reinterpret_cast<const float4*>(Wn + (size_t)e0.x * (NN * FF)));
            if (v1) w1 = __ldg(reinterpret_cast<const float4*>(Wn + (size_t)e1.x * (NN * FF)));
        }

        // C(k): consume first chunk
        float4 a0 = make_float4(0.f, 0.f, 0.f, 0.f);
        float4 a1 = make_float4(0.f, 0.f, 0.f, 0.f);
        const int cnt0 = min(64, curpe - curp);   // multiple of 8
        for (int j = 0; j < cnt0; j += 4) {
#pragma unroll
            for (int u = 0; u < 4; u++) {
                const int    sv = ssbuf[j + u];
                const float4 wc = wcbuf[j + u];
                const float4 xv = s_x[(sv << 5) + lane];
                if (u & 1) {
                    a1.x = fmaf(xv.x, wc.x, a1.x); a1.y = fmaf(xv.y, wc.y, a1.y);
                    a1.z = fmaf(xv.z, wc.z, a1.z); a1.w = fmaf(xv.w, wc.w, a1.w);
                } else {
                    a0.x = fmaf(xv.x, wc.x, a0.x); a0.y = fmaf(xv.y, wc.y, a0.y);
                    a0.z = fmaf(xv.z, wc.z, a0.z); a0.w = fmaf(xv.w, wc.w, a0.w);
                }
            }
        }

        // tail chunks (rows > 64 edges; rare) — non-pipelined fallback
        for (int base = curp + 64; base < curpe; base += 64) {
            __syncwarp();
            const int i0 = base + lane;
            const int i1 = base + 32 + lane;
            const bool v0 = (i0 < curpe);
            const bool v1 = (i1 < curpe);
            int2 f0e = v0 ? s_csr[i0] : make_int2(0, 0);
            int2 f1e = v1 ? s_csr[i1] : make_int2(0, 0);
            float4 u0 = make_float4(0.f, 0.f, 0.f, 0.f);
            float4 u1 = make_float4(0.f, 0.f, 0.f, 0.f);
            if (v0) u0 = __ldg(reinterpret_cast<const float4*>(curWn + (size_t)f0e.x * (NN * FF)));
            if (v1) u1 = __ldg(reinterpret_cast<const float4*>(curWn + (size_t)f1e.x * (NN * FF)));
            const float d0 = __int_as_float(f0e.y);
            const float d1 = __int_as_float(f1e.y);
            wcbuf[lane]      = make_float4(u0.x * d0, u0.y * d0, u0.z * d0, u0.w * d0);
            ssbuf[lane]      = f0e.x;
            wcbuf[32 + lane] = make_float4(u1.x * d1, u1.y * d1, u1.z * d1, u1.w * d1);
            ssbuf[32 + lane] = f1e.x;
            __syncwarp();
            const int cnt = min(64, curpe - base);
            for (int j = 0; j < cnt; j += 4) {
#pragma unroll
                for (int u = 0; u < 4; u++) {
                    const int    sv = ssbuf[j + u];
                    const float4 wc = wcbuf[j + u];
                    const float4 xv = s_x[(sv << 5) + lane];
                    if (u & 1) {
                        a1.x = fmaf(xv.x, wc.x, a1.x); a1.y = fmaf(xv.y, wc.y, a1.y);
                        a1.z = fmaf(xv.z, wc.z, a1.z); a1.w = fmaf(xv.w, wc.w, a1.w);
                    } else {
                        a0.x = fmaf(xv.x, wc.x, a0.x); a0.y = fmaf(xv.y, wc.y, a0.y);
                        a0.z = fmaf(xv.z, wc.z, a0.z); a0.w = fmaf(xv.w, wc.w, a0.w);
                    }
                }
            }
        }

        float4 r = make_float4(a0.x + a1.x, a0.y + a1.y,
                               a0.z + a1.z, a0.w + a1.w);
        *reinterpret_cast<float4*>(out + (size_t)(lane * NN + curn) * FF + f0) = r;
        __syncwarp();   // protect staging before next B
    }
}

// ---------------------------------------------------------------------------
extern "C" void kernel_launch(void* const* d_in, const int* in_sizes, int n_in,
                              void* d_out, int out_size) {
    const float* x     = (const float*)d_in[0];
    const float* W     = (const float*)d_in[1];
    const float* phase = (const float*)d_in[2];
    const int*   src   = (const int*)d_in[3];
    const int*   dst   = (const int*)d_in[4];
    float*       out   = (float*)d_out;

    const int smem = NN * BB * 16 + SPAN_CAP * 8;   // 180224 B dynamic
    cudaFuncSetAttribute(ep_compute_kernel,
                         cudaFuncAttributeMaxDynamicSharedMemorySize, smem);

    ep_prep_kernel<<<1, 1024>>>(phase, src, dst);
    ep_compute_kernel<<<128, 1024, smem>>>(x, W, out);
}

// round 14
// speedup vs baseline: 1.0429x; 1.0429x over previous
#include <cuda_runtime.h>
#include <cuda_pipeline.h>
#include <cstdint>

#define NN 256   // nodes
#define FF 256   // feature dim
#define BB 32    // batch
#define EE 8192  // edges
#define CSR_CAP 12288   // padded entries: EE + NN*7 = 9984 max

// Global padded CSR (built once by prep): rows padded to multiples of 8,
// pad entries {src=0, w=0.0f} are mathematical no-ops.
__device__ int g_row_ptr[NN + 1];
__device__ __align__(16) int2 g_csr[CSR_CAP];  // .x=src, .y=bits of cos/32

// ---------------------------------------------------------------------------
// Prep (1 block, 1024 threads): fully parallel — flag-reduce is64 detection,
// SMEM-atomic count, warp-shfl scan with row padding, atomic fill.
// ---------------------------------------------------------------------------
__global__ void __launch_bounds__(1024)
ep_prep_kernel(const float* __restrict__ phase,
               const int* __restrict__ src32,
               const int* __restrict__ dst32) {
    __shared__ int s_cnt[NN];
    __shared__ int s_rp[NN + 1];
    __shared__ int s_off[NN];
    __shared__ int s_bad;
    const int t    = threadIdx.x;
    const int warp = t >> 5;
    const int lane = t & 31;

    if (t == 0) s_bad = 0;
    if (t < NN) s_cnt[t] = 0;
    __syncthreads();

    // parallel int64-LE detection: 64 independent checks, flag write.
    if (t < 64) {
        const int lo = dst32[2 * t];
        const int hi = dst32[2 * t + 1];
        if (hi != 0 || lo < 0 || lo >= NN) s_bad = 1;
    }
    __syncthreads();
    const int stride = s_bad ? 1 : 2;     // bad pattern => plain int32

    for (int e = t; e < EE; e += 1024)
        atomicAdd(&s_cnt[dst32[e * stride]], 1);
    __syncthreads();

    // warp 0: exclusive scan of 256 padded counts (8 per lane).
    if (warp == 0) {
        const int i0 = lane * 8;
        int c[8], tot = 0;
#pragma unroll
        for (int u = 0; u < 8; u++) { c[u] = (s_cnt[i0 + u] + 7) & ~7; tot += c[u]; }
        int pre = tot;
        for (int off = 1; off < 32; off <<= 1) {
            const int v = __shfl_up_sync(0xFFFFFFFFu, pre, off);
            if (lane >= off) pre += v;
        }
        int acc = pre - tot;
#pragma unroll
        for (int u = 0; u < 8; u++) { s_rp[i0 + u] = acc; acc += c[u]; }
        if (lane == 31) s_rp[NN] = acc;
    }
    __syncthreads();

    // publish row_ptr, init fill cursors, zero pad slots.
    if (t < NN + 1) g_row_ptr[t] = s_rp[t];
    if (t < NN) {
        s_off[t] = s_rp[t];
        const int fe = s_rp[t] + s_cnt[t];
        const int re = s_rp[t + 1];
        for (int i = fe; i < re; i++) g_csr[i] = make_int2(0, 0);
    }
    __syncthreads();

    // fill with premultiplied weights cos(phase)/32.
    for (int e = t; e < EE; e += 1024) {
        const int d = dst32[e * stride];
        const int s = src32[e * stride];
        const int pos = atomicAdd(&s_off[d], 1);
        const float c = cosf(phase[s * NN + d]) * (1.0f / 32.0f);
        g_csr[pos] = make_int2(s, __float_as_int(c));
    }
}

// ---------------------------------------------------------------------------
// Compute (R7-proven structure, unchanged): block = (f-tile of 4 floats) x
// (half of dst range). Grid 128, 1024 threads (32 warps/SM, occ ~48%).
// SMEM: full x slice (128KB via cp.async) + per-warp edge staging (40KB).
// One warp per dst node (lane = batch), 4 nodes per warp. LOAD: lane = edge,
// up to 64 edges fetched with 2 divergent LDG.128s, premultiplied W*c staged
// in SMEM. CONSUME: lane = batch, broadcast LDS, 4 FMA/edge.
// ---------------------------------------------------------------------------
__global__ void __launch_bounds__(1024, 1)
ep_compute_kernel(const float* __restrict__ x,   // [B, N, F]
                  const float* __restrict__ W,   // [N, N, F]
                  float* __restrict__ out) {     // [B, N, F]
    extern __shared__ char s_raw[];
    float4* s_x = reinterpret_cast<float4*>(s_raw);   // [NN*BB], idx = s*32+b
    __shared__ float4 s_wc[32][64];   // staged W*c per warp (32KB)
    __shared__ int    s_ss[32][64];   // staged src per warp (8KB)
    __shared__ int    s_rp[128 + 1];

    const int bx     = blockIdx.x;               // 0..127
    const int f0     = (bx >> 1) * 4;
    const int n_base = (bx & 1) * 128;
    const int t      = threadIdx.x;

    // Kick x-tile staging (async, no register round-trip).
    for (int i = t; i < NN * BB; i += 1024) {
        const int s = i >> 5;
        const int b = i & 31;
        __pipeline_memcpy_async(&s_x[i],
                                x + (size_t)(b * NN + s) * FF + f0,
                                sizeof(float4));
    }
    __pipeline_commit();

    for (int i = t; i < 128 + 1; i += 1024) s_rp[i] = g_row_ptr[n_base + i];

    __pipeline_wait_prior(0);
    __syncthreads();

    const int warp = t >> 5;   // 0..31
    const int lane = t & 31;   // batch index (consume) / edge index (load)
    float4* wcbuf = s_wc[warp];
    int*    ssbuf = s_ss[warp];

    for (int k = 0; k < 4; k++) {
        const int nl = warp + (k << 5);          // local dst index 0..127
        const int n  = n_base + nl;
        const int p  = s_rp[nl];                 // absolute row start (mult 8)
        const int pe = s_rp[nl + 1];             // absolute row end

        float4 a0 = make_float4(0.f, 0.f, 0.f, 0.f);
        float4 a1 = make_float4(0.f, 0.f, 0.f, 0.f);
        const float* Wn = W + (size_t)n * FF + f0;

        for (int base = p; base < pe; base += 64) {
            // LOAD: lane = edge; 2 divergent LDG.128 in flight
            const int i0 = base + lane;
            const int i1 = base + 32 + lane;
            const bool v0 = (i0 < pe);
            const bool v1 = (i1 < pe);
            int2 e0 = make_int2(0, 0), e1 = make_int2(0, 0);
            if (v0) e0 = g_csr[i0];
            if (v1) e1 = g_csr[i1];
            float4 w0 = make_float4(0.f, 0.f, 0.f, 0.f);
            float4 w1 = make_float4(0.f, 0.f, 0.f, 0.f);
            if (v0) w0 = __ldg(reinterpret_cast<const float4*>(
                          Wn + (size_t)e0.x * (NN * FF)));
            if (v1) w1 = __ldg(reinterpret_cast<const float4*>(
                          Wn + (size_t)e1.x * (NN * FF)));
            const float c0 = __int_as_float(e0.y);
            const float c1 = __int_as_float(e1.y);
            wcbuf[lane]      = make_float4(w0.x * c0, w0.y * c0,
                                           w0.z * c0, w0.w * c0);
            ssbuf[lane]      = e0.x;
            wcbuf[32 + lane] = make_float4(w1.x * c1, w1.y * c1,
                                           w1.z * c1, w1.w * c1);
            ssbuf[32 + lane] = e1.x;
            __syncwarp();

            // CONSUME: lane = batch; broadcast LDS, 4 FMA/edge
            const int cnt = min(64, pe - base);  // multiple of 8
            for (int j = 0; j < cnt; j += 4) {
#pragma unroll
                for (int u = 0; u < 4; u++) {
                    const int    sv = ssbuf[j + u];
                    const float4 wc = wcbuf[j + u];
                    const float4 xv = s_x[(sv << 5) + lane];
                    if (u & 1) {
                        a1.x = fmaf(xv.x, wc.x, a1.x);
                        a1.y = fmaf(xv.y, wc.y, a1.y);
                        a1.z = fmaf(xv.z, wc.z, a1.z);
                        a1.w = fmaf(xv.w, wc.w, a1.w);
                    } else {
                        a0.x = fmaf(xv.x, wc.x, a0.x);
                        a0.y = fmaf(xv.y, wc.y, a0.y);
                        a0.z = fmaf(xv.z, wc.z, a0.z);
                        a0.w = fmaf(xv.w, wc.w, a0.w);
                    }
                }
            }
            __syncwarp();                        // before buffer reuse
        }

        float4 r = make_float4(a0.x + a1.x, a0.y + a1.y,
                               a0.z + a1.z, a0.w + a1.w);
        *reinterpret_cast<float4*>(out + (size_t)(lane * NN + n) * FF + f0) = r;
    }
}

// ---------------------------------------------------------------------------
extern "C" void kernel_launch(void* const* d_in, const int* in_sizes, int n_in,
                              void* d_out, int out_size) {
    const float* x     = (const float*)d_in[0];
    const float* W     = (const float*)d_in[1];
    const float* phase = (const float*)d_in[2];
    const int*   src   = (const int*)d_in[3];
    const int*   dst   = (const int*)d_in[4];
    float*       out   = (float*)d_out;

    const int smem = NN * BB * 16;   // 128KB dynamic x-tile
    cudaFuncSetAttribute(ep_compute_kernel,
                         cudaFuncAttributeMaxDynamicSharedMemorySize, smem);

    ep_prep_kernel<<<1, 1024>>>(phase, src, dst);
    ep_compute_kernel<<<128, 1024, smem>>>(x, W, out);
}

// round 15
// speedup vs baseline: 1.1075x; 1.0619x over previous
#include <cuda_runtime.h>
#include <cuda_pipeline.h>
#include <cstdint>

#define NN 256   // nodes
#define FF 256   // feature dim
#define BB 32    // batch
#define EE 8192  // edges
#define SPAN_CAP 6144   // local CSR entries per half (actual ~4100 + pads)

// ---------------------------------------------------------------------------
// Single fused kernel. Block = (f-tile of 4 floats) x (half of dst range).
// Grid 128 = 64 f-tiles x 2 halves. 1024 threads (32 warps/SM, occ ~48%).
//
// Phase 0 (overlapped with x-tile cp.async): build this half's dst-CSR in
// SMEM — PARALLEL is64 detection (flag-reduce, no serial load chain), count,
// warp-scan (rows padded to 8), pad-slot zeroing, atomic fill with
// premultiplied weight cos(phase)/32.
// Phase 1 (R7-proven): one warp per dst node (lane = batch). LOAD: lane =
// edge, up to 64 edges via 2 divergent LDG.128s, W*c staged in SMEM.
// CONSUME: broadcast LDS + conflict-free LDS.128 of x, 4 FMA/edge.
// ---------------------------------------------------------------------------
__global__ void __launch_bounds__(1024, 1)
ep_fused_kernel(const float* __restrict__ x,     // [B, N, F]
                const float* __restrict__ W,     // [N, N, F]
                const float* __restrict__ phase, // [N, N]
                const int* __restrict__ src32,
                const int* __restrict__ dst32,
                float* __restrict__ out) {       // [B, N, F]
    extern __shared__ char s_raw[];
    float4* s_x  = reinterpret_cast<float4*>(s_raw);               // 128KB
    int2*  s_csr = reinterpret_cast<int2*>(s_raw + NN * BB * 16);  // 48KB
    __shared__ float4 s_wc[32][64];   // staged W*c per warp (32KB)
    __shared__ int    s_ss[32][64];   // staged src per warp (8KB)
    __shared__ int    s_rp[128 + 1];
    __shared__ int    s_cnt[128];
    __shared__ int    s_off[128];
    __shared__ int    s_bad;

    const int bx     = blockIdx.x;               // 0..127
    const int f0     = (bx >> 1) * 4;
    const int n_base = (bx & 1) * 128;
    const int t      = threadIdx.x;
    const int warp   = t >> 5;
    const int lane   = t & 31;

    // ---- kick x-tile staging (async; overlaps the CSR build below) ----
    for (int i = t; i < NN * BB; i += 1024) {
        const int s = i >> 5;
        const int b = i & 31;
        __pipeline_memcpy_async(&s_x[i],
                                x + (size_t)(b * NN + s) * FF + f0,
                                sizeof(float4));
    }
    __pipeline_commit();

    // ---- parallel int64-LE detection (no serial chain) ----
    if (t == 0) s_bad = 0;
    if (t < 128) s_cnt[t] = 0;
    __syncthreads();
    if (t < 64) {
        const int lo = dst32[2 * t];
        const int hi = dst32[2 * t + 1];
        if (hi != 0 || lo < 0 || lo >= NN) s_bad = 1;
    }
    __syncthreads();
    const int stride = s_bad ? 1 : 2;    // bad int64 pattern => plain int32

    // ---- count this half's rows ----
    for (int e = t; e < EE; e += 1024) {
        const int d = dst32[e * stride];
        const int nl = d - n_base;
        if ((unsigned)nl < 128u) atomicAdd(&s_cnt[nl], 1);
    }
    __syncthreads();

    // ---- warp 0: exclusive scan of 128 padded counts ----
    if (warp == 0) {
        const int i0 = lane * 4;
        const int c0 = (s_cnt[i0 + 0] + 7) & ~7;
        const int c1 = (s_cnt[i0 + 1] + 7) & ~7;
        const int c2 = (s_cnt[i0 + 2] + 7) & ~7;
        const int c3 = (s_cnt[i0 + 3] + 7) & ~7;
        const int tot = c0 + c1 + c2 + c3;
        int pre = tot;
        for (int off = 1; off < 32; off <<= 1) {
            const int v = __shfl_up_sync(0xFFFFFFFFu, pre, off);
            if (lane >= off) pre += v;
        }
        const int base = pre - tot;
        s_rp[i0 + 0] = base;
        s_rp[i0 + 1] = base + c0;
        s_rp[i0 + 2] = base + c0 + c1;
        s_rp[i0 + 3] = base + c0 + c1 + c2;
        if (lane == 31) s_rp[128] = base + tot;
    }
    __syncthreads();

    // ---- init cursors; zero only the pad slots ----
    if (t < 128) {
        s_off[t] = s_rp[t];
        const int fe = s_rp[t] + s_cnt[t];   // real entries end
        const int re = s_rp[t + 1];          // padded row end
        for (int i = fe; i < re && i < SPAN_CAP; i++)
            s_csr[i] = make_int2(0, 0);
    }
    __syncthreads();

    // ---- fill: weight = cos(phase)/32 premultiplied ----
    for (int e = t; e < EE; e += 1024) {
        const int d = dst32[e * stride];
        const int nl = d - n_base;
        if ((unsigned)nl < 128u) {
            const int s = src32[e * stride];
            const int pos = atomicAdd(&s_off[nl], 1);
            if (pos < SPAN_CAP) {
                const float c = cosf(phase[s * NN + d]) * (1.0f / 32.0f);
                s_csr[pos] = make_int2(s, __float_as_int(c));
            }
        }
    }
    __pipeline_wait_prior(0);
    __syncthreads();

    // ---- phase 1: gather/scatter compute (R7-proven) ----
    float4* wcbuf = s_wc[warp];
    int*    ssbuf = s_ss[warp];

    for (int k = 0; k < 4; k++) {
        const int nl = warp + (k << 5);          // local dst index 0..127
        const int n  = n_base + nl;
        const int p  = s_rp[nl];                 // row start (mult of 8)
        const int pe = s_rp[nl + 1];             // row end

        float4 a0 = make_float4(0.f, 0.f, 0.f, 0.f);
        float4 a1 = make_float4(0.f, 0.f, 0.f, 0.f);
        const float* Wn = W + (size_t)n * FF + f0;

        for (int base = p; base < pe; base += 64) {
            // LOAD: lane = edge; 2 divergent LDG.128 in flight
            const int i0 = base + lane;
            const int i1 = base + 32 + lane;
            const bool v0 = (i0 < pe);
            const bool v1 = (i1 < pe);
            int2 e0 = make_int2(0, 0), e1 = make_int2(0, 0);
            if (v0) e0 = s_csr[i0];
            if (v1) e1 = s_csr[i1];
            float4 w0 = make_float4(0.f, 0.f, 0.f, 0.f);
            float4 w1 = make_float4(0.f, 0.f, 0.f, 0.f);
            if (v0) w0 = __ldg(reinterpret_cast<const float4*>(
                          Wn + (size_t)e0.x * (NN * FF)));
            if (v1) w1 = __ldg(reinterpret_cast<const float4*>(
                          Wn + (size_t)e1.x * (NN * FF)));
            const float c0 = __int_as_float(e0.y);
            const float c1 = __int_as_float(e1.y);
            wcbuf[lane]      = make_float4(w0.x * c0, w0.y * c0,
                                           w0.z * c0, w0.w * c0);
            ssbuf[lane]      = e0.x;
            wcbuf[32 + lane] = make_float4(w1.x * c1, w1.y * c1,
                                           w1.z * c1, w1.w * c1);
            ssbuf[32 + lane] = e1.x;
            __syncwarp();

            // CONSUME: lane = batch; broadcast LDS, 4 FMA/edge
            const int cnt = min(64, pe - base);  // multiple of 8
            for (int j = 0; j < cnt; j += 4) {
#pragma unroll
                for (int u = 0; u < 4; u++) {
                    const int    sv = ssbuf[j + u];
                    const float4 wc = wcbuf[j + u];
                    const float4 xv = s_x[(sv << 5) + lane];
                    if (u & 1) {
                        a1.x = fmaf(xv.x, wc.x, a1.x);
                        a1.y = fmaf(xv.y, wc.y, a1.y);
                        a1.z = fmaf(xv.z, wc.z, a1.z);
                        a1.w = fmaf(xv.w, wc.w, a1.w);
                    } else {
                        a0.x = fmaf(xv.x, wc.x, a0.x);
                        a0.y = fmaf(xv.y, wc.y, a0.y);
                        a0.z = fmaf(xv.z, wc.z, a0.z);
                        a0.w = fmaf(xv.w, wc.w, a0.w);
                    }
                }
            }
            __syncwarp();                        // before buffer reuse
        }

        float4 r = make_float4(a0.x + a1.x, a0.y + a1.y,
                               a0.z + a1.z, a0.w + a1.w);
        *reinterpret_cast<float4*>(out + (size_t)(lane * NN + n) * FF + f0) = r;
    }
}

// ---------------------------------------------------------------------------
extern "C" void kernel_launch(void* const* d_in, const int* in_sizes, int n_in,
                              void* d_out, int out_size) {
    const float* x     = (const float*)d_in[0];
    const float* W     = (const float*)d_in[1];
    const float* phase = (const float*)d_in[2];
    const int*   src   = (const int*)d_in[3];
    const int*   dst   = (const int*)d_in[4];
    float*       out   = (float*)d_out;

    // dynamic: 128KB x-tile + 48KB local CSR = 180224 B (static ~41KB).
    const int smem = NN * BB * 16 + SPAN_CAP * 8;
    cudaFuncSetAttribute(ep_fused_kernel,
                         cudaFuncAttributeMaxDynamicSharedMemorySize, smem);

    ep_fused_kernel<<<128, 1024, smem>>>(x, W, phase, src, dst, out);
}

// round 16
// speedup vs baseline: 1.1565x; 1.0442x over previous
#include <cuda_runtime.h>
#include <cuda_pipeline.h>
#include <cstdint>

#define NN 256   // nodes
#define FF 256   // feature dim
#define BB 32    // batch
#define EE 8192  // edges
#define SPAN_CAP 6144   // local CSR entries per half (actual ~4100 + pads)

// ---------------------------------------------------------------------------
// Single fused kernel. Block = (f-tile of 4 floats) x (half of dst range).
// Grid 128 = 64 f-tiles x 2 halves. 1024 threads (32 warps/SM, RF-capped).
//
// Phase 0: build this half's dst-CSR in SMEM (overlapped with x cp.async).
// Phase 1: one warp per dst node (lane = batch). W gathers go global->SMEM
// via per-lane cp.async into a double-buffered 32-edge staging area: chunk
// k+1's 32 gathers are IN FLIGHT while chunk k is consumed — W never
// transits registers, so the pipeline costs no register pressure.
// CONSUME: broadcast LDS of edge record + staged W, conflict-free LDS.128
// of x, w*c fold + 4 FMA per edge.
// ---------------------------------------------------------------------------
__global__ void __launch_bounds__(1024, 1)
ep_fused_kernel(const float* __restrict__ x,     // [B, N, F]
                const float* __restrict__ W,     // [N, N, F]
                const float* __restrict__ phase, // [N, N]
                const int* __restrict__ src32,
                const int* __restrict__ dst32,
                float* __restrict__ out) {       // [B, N, F]
    extern __shared__ char s_raw[];
    float4* s_x  = reinterpret_cast<float4*>(s_raw);               // 128KB
    int2*  s_csr = reinterpret_cast<int2*>(s_raw + NN * BB * 16);  // 48KB
    __shared__ float4 s_wr[32][2][32];  // per-warp double-buffered W staging (32KB)
    __shared__ int    s_rp[128 + 1];
    __shared__ int    s_cnt[128];
    __shared__ int    s_off[128];
    __shared__ int    s_bad;

    const int bx     = blockIdx.x;               // 0..127
    const int f0     = (bx >> 1) * 4;
    const int n_base = (bx & 1) * 128;
    const int t      = threadIdx.x;
    const int warp   = t >> 5;
    const int lane   = t & 31;

    // ---- kick x-tile staging (async; overlaps the CSR build below) ----
    for (int i = t; i < NN * BB; i += 1024) {
        const int s = i >> 5;
        const int b = i & 31;
        __pipeline_memcpy_async(&s_x[i],
                                x + (size_t)(b * NN + s) * FF + f0,
                                sizeof(float4));
    }
    __pipeline_commit();

    // ---- parallel int64-LE detection ----
    if (t == 0) s_bad = 0;
    if (t < 128) s_cnt[t] = 0;
    __syncthreads();
    if (t < 64) {
        const int lo = dst32[2 * t];
        const int hi = dst32[2 * t + 1];
        if (hi != 0 || lo < 0 || lo >= NN) s_bad = 1;
    }
    __syncthreads();
    const int stride = s_bad ? 1 : 2;

    // ---- count this half's rows ----
    for (int e = t; e < EE; e += 1024) {
        const int d = dst32[e * stride];
        const int nl = d - n_base;
        if ((unsigned)nl < 128u) atomicAdd(&s_cnt[nl], 1);
    }
    __syncthreads();

    // ---- warp 0: exclusive scan of 128 padded counts ----
    if (warp == 0) {
        const int i0 = lane * 4;
        const int c0 = (s_cnt[i0 + 0] + 7) & ~7;
        const int c1 = (s_cnt[i0 + 1] + 7) & ~7;
        const int c2 = (s_cnt[i0 + 2] + 7) & ~7;
        const int c3 = (s_cnt[i0 + 3] + 7) & ~7;
        const int tot = c0 + c1 + c2 + c3;
        int pre = tot;
        for (int off = 1; off < 32; off <<= 1) {
            const int v = __shfl_up_sync(0xFFFFFFFFu, pre, off);
            if (lane >= off) pre += v;
        }
        const int base = pre - tot;
        s_rp[i0 + 0] = base;
        s_rp[i0 + 1] = base + c0;
        s_rp[i0 + 2] = base + c0 + c1;
        s_rp[i0 + 3] = base + c0 + c1 + c2;
        if (lane == 31) s_rp[128] = base + tot;
    }
    __syncthreads();

    // ---- init cursors; zero only the pad slots ----
    if (t < 128) {
        s_off[t] = s_rp[t];
        const int fe = s_rp[t] + s_cnt[t];
        const int re = s_rp[t + 1];
        for (int i = fe; i < re && i < SPAN_CAP; i++)
            s_csr[i] = make_int2(0, 0);
    }
    __syncthreads();

    // ---- fill: weight = cos(phase)/32 premultiplied into record ----
    for (int e = t; e < EE; e += 1024) {
        const int d = dst32[e * stride];
        const int nl = d - n_base;
        if ((unsigned)nl < 128u) {
            const int s = src32[e * stride];
            const int pos = atomicAdd(&s_off[nl], 1);
            if (pos < SPAN_CAP) {
                const float c = cosf(phase[s * NN + d]) * (1.0f / 32.0f);
                s_csr[pos] = make_int2(s, __float_as_int(c));
            }
        }
    }
    __pipeline_wait_prior(0);   // drain x staging
    __syncthreads();

    // ---- phase 1: cp.async double-buffered gather/scatter ----
    // flat 32-edge chunk enumeration over this warp's 4 nodes
    int en_k   = 0;
    int en_pos = s_rp[warp];
    int en_end = s_rp[warp + 1];

    auto fetch = [&](int& ck, int& cb, int& cc) {
        while (en_k < 4 && en_pos >= en_end) {
            ++en_k;
            if (en_k < 4) {
                const int nl = warp + (en_k << 5);
                en_pos = s_rp[nl];
                en_end = s_rp[nl + 1];
            }
        }
        if (en_k >= 4) { ck = 4; cb = 0; cc = 0; return; }
        ck = en_k;
        cb = en_pos;
        cc = min(32, en_end - en_pos);   // multiple of 8
        en_pos += 32;
    };

    auto issue = [&](int ck, int cb, int cc, int buf) {
        if (ck < 4 && lane < cc) {
            const int2 e = s_csr[cb + lane];
            const float* p = W + (size_t)(n_base + warp + (ck << 5)) * FF + f0
                               + (size_t)e.x * (NN * FF);
            __pipeline_memcpy_async(&s_wr[warp][buf][lane], p, sizeof(float4));
        }
        __pipeline_commit();
    };

    auto storeOut = [&](int k, float4 r) {
        const int n = n_base + warp + (k << 5);
        *reinterpret_cast<float4*>(out + (size_t)(lane * NN + n) * FF + f0) = r;
    };

    int c0k, c0b, c0c, c1k, c1b, c1c;
    fetch(c0k, c0b, c0c); issue(c0k, c0b, c0c, 0);
    fetch(c1k, c1b, c1c); issue(c1k, c1b, c1c, 1);

    int curk = c0k, curb = c0b, curc = c0c;
    int nxtk = c1k, nxtb = c1b, nxtc = c1c;
    int buf  = 0;
    int outk = 0;
    float4 a0 = make_float4(0.f, 0.f, 0.f, 0.f);
    float4 a1 = make_float4(0.f, 0.f, 0.f, 0.f);

    while (curk < 4) {
        __pipeline_wait_prior(1);    // cur's group complete (this lane)
        __syncwarp();                // => all lanes' copies complete + visible

        if (curk != outk) {          // node boundary: flush accumulator
            storeOut(outk, make_float4(a0.x + a1.x, a0.y + a1.y,
                                       a0.z + a1.z, a0.w + a1.w));
            for (int z = outk + 1; z < curk; ++z)
                storeOut(z, make_float4(0.f, 0.f, 0.f, 0.f));
            a0 = make_float4(0.f, 0.f, 0.f, 0.f);
            a1 = make_float4(0.f, 0.f, 0.f, 0.f);
            outk = curk;
        }

        const float4* wbuf = s_wr[warp][buf];
        for (int j = 0; j < curc; j += 4) {
#pragma unroll
            for (int u = 0; u < 4; ++u) {
                const int2   e  = s_csr[curb + j + u];   // broadcast LDS
                const float4 wv = wbuf[j + u];           // broadcast LDS
                const float  cc = __int_as_float(e.y);
                const float4 xv = s_x[(e.x << 5) + lane];
                if (u & 1) {
                    a1.x = fmaf(xv.x, wv.x * cc, a1.x);
                    a1.y = fmaf(xv.y, wv.y * cc, a1.y);
                    a1.z = fmaf(xv.z, wv.z * cc, a1.z);
                    a1.w = fmaf(xv.w, wv.w * cc, a1.w);
                } else {
                    a0.x = fmaf(xv.x, wv.x * cc, a0.x);
                    a0.y = fmaf(xv.y, wv.y * cc, a0.y);
                    a0.z = fmaf(xv.z, wv.z * cc, a0.z);
                    a0.w = fmaf(xv.w, wv.w * cc, a0.w);
                }
            }
        }
        __syncwarp();                // all lanes done with buf before reissue

        int nk, nb, nc;
        fetch(nk, nb, nc);
        issue(nk, nb, nc, buf);      // refill freed buffer
        curk = nxtk; curb = nxtb; curc = nxtc;
        nxtk = nk;   nxtb = nb;   nxtc = nc;
        buf ^= 1;
    }

    // final flush (also covers empty trailing nodes)
    storeOut(outk, make_float4(a0.x + a1.x, a0.y + a1.y,
                               a0.z + a1.z, a0.w + a1.w));
    for (int z = outk + 1; z < 4; ++z)
        storeOut(z, make_float4(0.f, 0.f, 0.f, 0.f));
}

// ---------------------------------------------------------------------------
extern "C" void kernel_launch(void* const* d_in, const int* in_sizes, int n_in,
                              void* d_out, int out_size) {
    const float* x     = (const float*)d_in[0];
    const float* W     = (const float*)d_in[1];
    const float* phase = (const float*)d_in[2];
    const int*   src   = (const int*)d_in[3];
    const int*   dst   = (const int*)d_in[4];
    float*       out   = (float*)d_out;

    // dynamic: 128KB x-tile + 48KB local CSR (static ~34KB incl. staging).
    const int smem = NN * BB * 16 + SPAN_CAP * 8;
    cudaFuncSetAttribute(ep_fused_kernel,
                         cudaFuncAttributeMaxDynamicSharedMemorySize, smem);

    ep_fused_kernel<<<128, 1024, smem>>>(x, W, phase, src, dst, out);
}